// round 13
// baseline (speedup 1.0000x reference)
#include <cuda_runtime.h>
#include <cuda_fp16.h>
#include <math.h>

#define BB 4
#define LL 2048
#define DD 1024
#define HH 16
#define DH 64
#define NS 16
#define EE 16
#define FF 4096

// ---------------- scratch ----------------
__device__ __half g_khh [BB*LL*DD];
__device__ __half g_vhh [BB*LL*DD];
__device__ float  g_qh1 [NS*DD];
__device__ float  g_o   [BB*NS*DD];
__device__ float  g_hn  [BB*NS*DD];
__device__ float  g_ug  [BB*EE*FF];
__device__ float  g_qh2 [BB*LL*DD];
__device__ float  g_kh2 [BB*NS*DD];
__device__ float  g_vh2 [BB*NS*DD];
__device__ float  g_sc  [BB*HH*NS*LL];
__device__ float  g_part[16*BB*NS*DD];
__device__ float  g_skp [8*64*DD];
__device__ float  g_w2p [8*BB*EE*DD];
__device__ float  g_kvp [2*8*64*DD];
__device__ __half g_xh  [BB*LL*DD];
__device__ __half g_wh  [4*DD*DD];
__device__ __half g_a2h [BB*LL*DD];

__device__ __forceinline__ void cpa16(void* dst, const void* src) {
    unsigned d = (unsigned)__cvta_generic_to_shared(dst);
    asm volatile("cp.async.cg.shared.global [%0], [%1], 16;\n" :: "r"(d), "l"(src));
}
__device__ __forceinline__ void cpa_commit() {
    asm volatile("cp.async.commit_group;\n" ::: "memory");
}
__device__ __forceinline__ void cpa_wait2() {
    asm volatile("cp.async.wait_group 2;\n" ::: "memory");
}
__device__ __forceinline__ float silu_f(float x) { return x / (1.f + __expf(-x)); }

// ---------------- fp16 conversion pre-passes ----------------
__global__ void cvt_f16(const float* __restrict__ src, __half* __restrict__ dst, int n4)
{
    int i = blockIdx.x * 256 + threadIdx.x;
    if (i < n4) {
        float4 v = *(const float4*)&src[(size_t)i * 4];
        __half2 h0 = __floats2half2_rn(v.x, v.y);
        __half2 h1 = __floats2half2_rn(v.z, v.w);
        __half2* d2 = (__half2*)(dst + (size_t)i * 4);
        d2[0] = h0; d2[1] = h1;
    }
}

__global__ void cvt_w4_f16(const float* __restrict__ s0, const float* __restrict__ s1,
                           const float* __restrict__ s2, const float* __restrict__ s3,
                           __half* __restrict__ dst)
{
    int i = blockIdx.x * 256 + threadIdx.x;
    int y = blockIdx.y;
    const float* s = (y == 0) ? s0 : (y == 1) ? s1 : (y == 2) ? s2 : s3;
    float4 v = *(const float4*)&s[(size_t)i * 4];
    __half2 h0 = __floats2half2_rn(v.x, v.y);
    __half2 h1 = __floats2half2_rn(v.z, v.w);
    __half2* d2 = (__half2*)(dst + (size_t)y * DD * DD + (size_t)i * 4);
    d2[0] = h0; d2[1] = h1;
}

// ======================= fp16 tensor-core GEMM (m16n8k16 + ldmatrix) =======================
#define APITCH_H 40
#define BPITCH_H 136
#define ASTG_H (128*APITCH_H)
#define BSTG_H (32*BPITCH_H)
#define GEMM_SMEM_H (4 * (ASTG_H + BSTG_H) * 2)

template<typename OutT>
__global__ __launch_bounds__(256)
void gemm_f16(const __half* __restrict__ A, const __half* __restrict__ W,
              const float* __restrict__ bias, OutT* __restrict__ C,
              int M, int N, int K)
{
    extern __shared__ __half smh[];
    __half* As = smh;
    __half* Bs = smh + 4 * ASTG_H;

    const int tid  = threadIdx.x;
    const int wid  = tid >> 5;
    const int lane = tid & 31;
    const int g    = lane >> 2;
    const int tig  = lane & 3;
    const int wm0  = (wid >> 2) * 64;
    const int wn0  = (wid & 3) * 32;
    const int row0 = blockIdx.y * 128;
    const int col0 = blockIdx.x * 128;

    const int la = lane & 15;
    const int lb = (lane >> 4) * 8;

    const unsigned smem_base = (unsigned)__cvta_generic_to_shared(smh);
    const unsigned bs_base   = smem_base + 4 * ASTG_H * 2;

    const int NT = K >> 5;

    auto load_stage = [&](int tile, int st) {
        const int k0 = tile * 32;
        __half* as = As + st * ASTG_H;
        __half* bs = Bs + st * BSTG_H;
#pragma unroll
        for (int p = 0; p < 2; p++) {
            int c = tid + p * 256;
            int ar = c >> 2, ac = (c & 3) * 8;
            cpa16(&as[ar * APITCH_H + ac], &A[(size_t)(row0 + ar) * K + k0 + ac]);
            int br = c >> 4, bc = (c & 15) * 8;
            cpa16(&bs[br * BPITCH_H + bc], &W[(size_t)(k0 + br) * N + col0 + bc]);
        }
    };

    float acc[4][4][4];
#pragma unroll
    for (int i = 0; i < 4; i++)
#pragma unroll
        for (int j = 0; j < 4; j++)
#pragma unroll
            for (int c = 0; c < 4; c++) acc[i][j][c] = 0.f;

    load_stage(0, 0); cpa_commit();
    load_stage(1, 1); cpa_commit();
    load_stage(2, 2); cpa_commit();

    for (int i = 0; i < NT; i++) {
        cpa_wait2();
        __syncthreads();

        const int st = i & 3;
        const unsigned aBase = smem_base + (st * ASTG_H) * 2;
        const unsigned bBase = bs_base   + (st * BSTG_H) * 2;

#pragma unroll
        for (int ks = 0; ks < 2; ks++) {
            unsigned af[4][4];
#pragma unroll
            for (int mt = 0; mt < 4; mt++) {
                unsigned addr = aBase + (((wm0 + mt * 16 + la) * APITCH_H) + ks * 16 + lb) * 2;
                asm volatile("ldmatrix.sync.aligned.m8n8.x4.shared.b16 {%0,%1,%2,%3}, [%4];"
                             : "=r"(af[mt][0]), "=r"(af[mt][1]), "=r"(af[mt][2]), "=r"(af[mt][3])
                             : "r"(addr));
            }
            unsigned bf[4][2];
#pragma unroll
            for (int np = 0; np < 2; np++) {
                unsigned addr = bBase + (((ks * 16 + la) * BPITCH_H) + wn0 + np * 16 + lb) * 2;
                asm volatile("ldmatrix.sync.aligned.m8n8.x4.trans.shared.b16 {%0,%1,%2,%3}, [%4];"
                             : "=r"(bf[np * 2][0]), "=r"(bf[np * 2][1]),
                               "=r"(bf[np * 2 + 1][0]), "=r"(bf[np * 2 + 1][1])
                             : "r"(addr));
            }
#pragma unroll
            for (int mt = 0; mt < 4; mt++)
#pragma unroll
                for (int nt = 0; nt < 4; nt++) {
                    asm volatile(
                        "mma.sync.aligned.m16n8k16.row.col.f32.f16.f16.f32 "
                        "{%0,%1,%2,%3}, {%4,%5,%6,%7}, {%8,%9}, {%0,%1,%2,%3};\n"
                        : "+f"(acc[mt][nt][0]), "+f"(acc[mt][nt][1]),
                          "+f"(acc[mt][nt][2]), "+f"(acc[mt][nt][3])
                        : "r"(af[mt][0]), "r"(af[mt][1]), "r"(af[mt][2]), "r"(af[mt][3]),
                          "r"(bf[nt][0]), "r"(bf[nt][1]));
                }
        }

        if (i + 3 < NT) load_stage(i + 3, (i + 3) & 3);
        cpa_commit();
    }

#pragma unroll
    for (int mt = 0; mt < 4; mt++) {
#pragma unroll
        for (int nt = 0; nt < 4; nt++) {
            int r = row0 + wm0 + mt * 16 + g;
            int c = col0 + wn0 + nt * 8 + tig * 2;
            float b0v = bias[c], b1v = bias[c + 1];
            float o00 = acc[mt][nt][0] + b0v, o01 = acc[mt][nt][1] + b1v;
            float o10 = acc[mt][nt][2] + b0v, o11 = acc[mt][nt][3] + b1v;
            if constexpr (sizeof(OutT) == 4) {
                *(float2*)&C[(size_t)r * N + c] = make_float2(o00, o01);
                *(float2*)&C[(size_t)(r + 8) * N + c] = make_float2(o10, o11);
            } else {
                *(__half2*)&C[(size_t)r * N + c] = __floats2half2_rn(o00, o01);
                *(__half2*)&C[(size_t)(r + 8) * N + c] = __floats2half2_rn(o10, o11);
            }
        }
    }
}

// ======================= direct skinny GEMM for qh1 (M=16, no split-K) =======================
// grid (DD/64), 256 threads; each block computes 16x64 outputs with full K loop
__global__ void gemm_q1(const float* __restrict__ A, const float* __restrict__ W,
                        const float* __restrict__ bias, float* __restrict__ C)
{
    __shared__ float As[16][DD / 4];   // staged in 4 chunks
    const int tid = threadIdx.x;
    const int n  = blockIdx.x * 64 + (tid & 63);
    const int mg = tid >> 6;           // 0..3
    float acc[4] = {0.f, 0.f, 0.f, 0.f};

    for (int kc = 0; kc < 4; kc++) {
        const int k0 = kc * 256;
        for (int idx = tid; idx < 16 * 64; idx += 256) {
            int m = idx >> 6, c4 = (idx & 63) * 4;
            *(float4*)&As[m][c4] = *(const float4*)&A[(size_t)m * DD + k0 + c4];
        }
        __syncthreads();
#pragma unroll 4
        for (int k = 0; k < 256; k++) {
            float wv = __ldg(&W[(size_t)(k0 + k) * DD + n]);
#pragma unroll
            for (int r = 0; r < 4; r++) acc[r] += As[mg + 4 * r][k] * wv;
        }
        __syncthreads();
    }
    float bv = bias[n];
#pragma unroll
    for (int r = 0; r < 4; r++)
        C[(size_t)(mg + 4 * r) * DD + n] = acc[r] + bv;
}

// skinny GEMM with A = sum of 16 AV partials (fuses disp_reduce)
__global__ void gemm_skinny_red(const float* __restrict__ avp, const float* __restrict__ W,
                                float* __restrict__ part)
{
    __shared__ float As[64][132];
    const int tid = threadIdx.x;
    const int ks = blockIdx.y;
    const int n  = blockIdx.x * 64 + (tid & 63);
    const int mg = tid >> 6;
    const int k0 = ks * 128;

    for (int idx = tid; idx < 64 * 32; idx += 256) {
        int m = idx >> 5, c4 = (idx & 31) * 4;
        float4 s = make_float4(0.f, 0.f, 0.f, 0.f);
#pragma unroll
        for (int z = 0; z < 16; z++) {
            float4 p = *(const float4*)&avp[(size_t)z * (BB * NS * DD) + (size_t)m * DD + k0 + c4];
            s.x += p.x; s.y += p.y; s.z += p.z; s.w += p.w;
        }
        *(float4*)&As[m][c4] = s;
    }
    __syncthreads();

    float acc[16];
#pragma unroll
    for (int r = 0; r < 16; r++) acc[r] = 0.f;
#pragma unroll 4
    for (int k = 0; k < 128; k++) {
        float wv = __ldg(&W[(size_t)(k0 + k) * DD + n]);
#pragma unroll
        for (int r = 0; r < 16; r++) acc[r] += As[mg + 4 * r][k] * wv;
    }
#pragma unroll
    for (int r = 0; r < 16; r++)
        part[((size_t)ks * 64 + mg + 4 * r) * DD + n] = acc[r];
}

// dual skinny GEMM with A = o + b2 + sum8(w2 partials), fused in A-load (fuses w2_reduce)
__global__ void gemm_skinny_dual_red(const float* __restrict__ o, const float* __restrict__ w2p,
                                     const float* __restrict__ b2,
                                     const float* __restrict__ W0, const float* __restrict__ W1,
                                     float* __restrict__ p0, float* __restrict__ p1)
{
    __shared__ float As[64][132];
    const float* W = blockIdx.z ? W1 : W0;
    float* part    = blockIdx.z ? p1 : p0;
    const int tid = threadIdx.x;
    const int ks = blockIdx.y;
    const int n  = blockIdx.x * 64 + (tid & 63);
    const int mg = tid >> 6;
    const int k0 = ks * 128;

    for (int idx = tid; idx < 64 * 32; idx += 256) {
        int m = idx >> 5, c4 = (idx & 31) * 4;
        int e = m & (NS - 1);
        float4 s = *(const float4*)&o[(size_t)m * DD + k0 + c4];
        float4 bb = *(const float4*)&b2[(size_t)e * DD + k0 + c4];
        s.x += bb.x; s.y += bb.y; s.z += bb.z; s.w += bb.w;
#pragma unroll
        for (int z = 0; z < 8; z++) {
            float4 p = *(const float4*)&w2p[(size_t)z * (BB * EE * DD) + (size_t)m * DD + k0 + c4];
            s.x += p.x; s.y += p.y; s.z += p.z; s.w += p.w;
        }
        *(float4*)&As[m][c4] = s;
    }
    __syncthreads();

    float acc[16];
#pragma unroll
    for (int r = 0; r < 16; r++) acc[r] = 0.f;
#pragma unroll 4
    for (int k = 0; k < 128; k++) {
        float wv = __ldg(&W[(size_t)(k0 + k) * DD + n]);
#pragma unroll
        for (int r = 0; r < 16; r++) acc[r] += As[mg + 4 * r][k] * wv;
    }
#pragma unroll
    for (int r = 0; r < 16; r++)
        part[((size_t)ks * 64 + mg + 4 * r) * DD + n] = acc[r];
}

__global__ void skinny_reduce_dual(const float* __restrict__ p0, const float* __restrict__ p1,
                                   const float* __restrict__ bias0, const float* __restrict__ bias1,
                                   float* __restrict__ C0, float* __restrict__ C1)
{
    int i = blockIdx.x * 256 + threadIdx.x;
    const float* part = blockIdx.y ? p1 : p0;
    const float* bias = blockIdx.y ? bias1 : bias0;
    float* C          = blockIdx.y ? C1 : C0;
    int n = i & (DD - 1);
    int m = i / DD;
    float s = bias[n];
#pragma unroll
    for (int z = 0; z < 8; z++) s += part[((size_t)z * 64 + m) * DD + n];
    C[i] = s;
}

// fused: o = bias + slot_query + sum(skinny partials); hn = LayerNorm(o)
__global__ void skred_addsq_ln(const float* __restrict__ part, const float* __restrict__ bias,
                               const float* __restrict__ sq, float* __restrict__ o,
                               const float* __restrict__ gam, const float* __restrict__ bet,
                               float* __restrict__ hn)
{
    const int row = blockIdx.x;            // b*NS + s  (expert e == s)
    const int e = row & (NS - 1);
    const int tid = threadIdx.x;
    const int d4 = tid * 4;

    float4 v = *(const float4*)&bias[d4];
    float4 sv = *(const float4*)&sq[(size_t)e * DD + d4];
    v.x += sv.x; v.y += sv.y; v.z += sv.z; v.w += sv.w;
#pragma unroll
    for (int z = 0; z < 8; z++) {
        float4 p = *(const float4*)&part[((size_t)z * 64 + row) * DD + d4];
        v.x += p.x; v.y += p.y; v.z += p.z; v.w += p.w;
    }
    *(float4*)&o[(size_t)row * DD + d4] = v;

    float s1 = v.x + v.y + v.z + v.w;
    float s2 = v.x * v.x + v.y * v.y + v.z * v.z + v.w * v.w;
    __shared__ float r1[8], r2[8];
#pragma unroll
    for (int off = 16; off; off >>= 1) {
        s1 += __shfl_xor_sync(0xffffffffu, s1, off);
        s2 += __shfl_xor_sync(0xffffffffu, s2, off);
    }
    int wd = tid >> 5, ln = tid & 31;
    if (!ln) { r1[wd] = s1; r2[wd] = s2; }
    __syncthreads();
    if (tid < 32) {
        s1 = (ln < 8) ? r1[ln] : 0.f;
        s2 = (ln < 8) ? r2[ln] : 0.f;
#pragma unroll
        for (int off = 4; off; off >>= 1) {
            s1 += __shfl_xor_sync(0xffffffffu, s1, off);
            s2 += __shfl_xor_sync(0xffffffffu, s2, off);
        }
        if (!ln) { r1[0] = s1; r2[0] = s2; }
    }
    __syncthreads();
    float mu  = r1[0] * (1.f / DD);
    float var = r2[0] * (1.f / DD) - mu * mu;
    float inv = rsqrtf(var + 1e-5f);
    float4 gm = *(const float4*)&gam[(size_t)e * DD + d4];
    float4 bt = *(const float4*)&bet[(size_t)e * DD + d4];
    float4 hh;
    hh.x = (v.x - mu) * inv * gm.x + bt.x;
    hh.y = (v.y - mu) * inv * gm.y + bt.y;
    hh.z = (v.z - mu) * inv * gm.z + bt.z;
    hh.w = (v.w - mu) * inv * gm.w + bt.w;
    *(float4*)&hn[(size_t)row * DD + d4] = hh;
}

// ======================= dispatch attention (fp16 K/V) =======================
__global__ void disp_scores(const float* __restrict__ qh, const __half* __restrict__ khh,
                            float* __restrict__ sc)
{
    __shared__ float q[16][64];
    __shared__ float kt[128][65];
    const int j0 = blockIdx.x * 128;
    const int h  = blockIdx.y;
    const int b  = blockIdx.z;
    const int tid = threadIdx.x;

    for (int i = tid; i < NS * DH; i += 256) {
        int s = i >> 6, d = i & 63;
        q[s][d] = qh[(size_t)s * DD + h * DH + d];
    }
#pragma unroll
    for (int p = 0; p < 8; p++) {
        int idx = tid + p * 256;
        int jj = idx >> 4, d4 = (idx & 15) * 4;
        const __half2* src = (const __half2*)&khh[((size_t)b * LL + j0 + jj) * DD + h * DH + d4];
        float2 f0 = __half22float2(src[0]);
        float2 f1 = __half22float2(src[1]);
        kt[jj][d4 + 0] = f0.x; kt[jj][d4 + 1] = f0.y;
        kt[jj][d4 + 2] = f1.x; kt[jj][d4 + 3] = f1.y;
    }
    __syncthreads();

#pragma unroll
    for (int p = 0; p < 8; p++) {
        int idx = tid + p * 256;
        int s = idx >> 7, jj = idx & 127;
        float dot = 0.f;
#pragma unroll
        for (int d = 0; d < DH; d++) dot += q[s][d] * kt[jj][d];
        sc[(((size_t)b * HH + h) * NS + s) * LL + j0 + jj] = dot * 0.125f;
    }
}

__global__ void disp_softmax(float* __restrict__ sc)
{
    __shared__ float red[9];
    const int tid = threadIdx.x;
    float* r = sc + (size_t)blockIdx.x * LL;
    float v[8];
    float mx = -1e30f;
#pragma unroll
    for (int i = 0; i < 8; i++) { v[i] = r[tid + i * 256]; mx = fmaxf(mx, v[i]); }
#pragma unroll
    for (int o = 16; o; o >>= 1) mx = fmaxf(mx, __shfl_xor_sync(0xffffffffu, mx, o));
    int wd = tid >> 5, ln = tid & 31;
    if (!ln) red[wd] = mx;
    __syncthreads();
    if (tid < 32) {
        mx = (ln < 8) ? red[ln] : -1e30f;
#pragma unroll
        for (int o = 4; o; o >>= 1) mx = fmaxf(mx, __shfl_xor_sync(0xffffffffu, mx, o));
        if (!ln) red[8] = mx;
    }
    __syncthreads();
    mx = red[8];
    float sum = 0.f;
#pragma unroll
    for (int i = 0; i < 8; i++) { v[i] = __expf(v[i] - mx); sum += v[i]; }
#pragma unroll
    for (int o = 16; o; o >>= 1) sum += __shfl_xor_sync(0xffffffffu, sum, o);
    __syncthreads();
    if (!ln) red[wd] = sum;
    __syncthreads();
    if (tid < 32) {
        sum = (ln < 8) ? red[ln] : 0.f;
#pragma unroll
        for (int o = 4; o; o >>= 1) sum += __shfl_xor_sync(0xffffffffu, sum, o);
        if (!ln) red[8] = sum;
    }
    __syncthreads();
    float inv = 1.f / red[8];
#pragma unroll
    for (int i = 0; i < 8; i++) r[tid + i * 256] = v[i] * inv;
}

__global__ void disp_av(const float* __restrict__ sc, const __half* __restrict__ vhh,
                        float* __restrict__ part)
{
    __shared__ float p[16][132];
    __shared__ float vt[128][65];
    const int h = blockIdx.x, b = blockIdx.y, jz = blockIdx.z;
    const int j0 = jz * 128;
    const int tid = threadIdx.x;

#pragma unroll
    for (int q = 0; q < 2; q++) {
        int idx = tid + q * 256;
        int s = idx >> 5, j4 = (idx & 31) * 4;
        float4 v = *(const float4*)&sc[(((size_t)b * HH + h) * NS + s) * LL + j0 + j4];
        *(float4*)&p[s][j4] = v;
    }
#pragma unroll
    for (int q = 0; q < 8; q++) {
        int idx = tid + q * 256;
        int jj = idx >> 4, d4 = (idx & 15) * 4;
        const __half2* src = (const __half2*)&vhh[((size_t)b * LL + j0 + jj) * DD + h * DH + d4];
        float2 f0 = __half22float2(src[0]);
        float2 f1 = __half22float2(src[1]);
        vt[jj][d4 + 0] = f0.x; vt[jj][d4 + 1] = f0.y;
        vt[jj][d4 + 2] = f1.x; vt[jj][d4 + 3] = f1.y;
    }
    __syncthreads();

    float acc[4] = {0.f, 0.f, 0.f, 0.f};
#pragma unroll 4
    for (int jj = 0; jj < 128; jj++) {
#pragma unroll
        for (int k = 0; k < 4; k++) {
            int idx = tid + k * 256;
            int s = idx >> 6, d = idx & 63;
            acc[k] += p[s][jj] * vt[jj][d];
        }
    }
#pragma unroll
    for (int k = 0; k < 4; k++) {
        int idx = tid + k * 256;
        int s = idx >> 6, d = idx & 63;
        part[(size_t)jz * (BB * NS * DD) + ((size_t)b * NS + s) * DD + h * DH + d] = acc[k];
    }
}

// ---------------- expert up/gate (default-cache streaming) ----------------
__global__ void expert_ug(const float* __restrict__ hn,
                          const float* __restrict__ W1, const float* __restrict__ b1,
                          const float* __restrict__ Wg, const float* __restrict__ bg,
                          float* __restrict__ ug)
{
    const int e = blockIdx.y;
    const int f = blockIdx.x * 128 + threadIdx.x;
    __shared__ float hs[BB][DD];
    for (int i = threadIdx.x; i < BB * DD / 4; i += 128) {
        int b = (i * 4) >> 10, d4 = (i * 4) & 1023;
        *(float4*)&hs[b][d4] = *(const float4*)&hn[((size_t)b * NS + e) * DD + d4];
    }
    __syncthreads();

    const float* w1 = W1 + (size_t)e * DD * FF + f;
    const float* wg = Wg + (size_t)e * DD * FF + f;
    float au[BB] = {0.f, 0.f, 0.f, 0.f};
    float ag[BB] = {0.f, 0.f, 0.f, 0.f};
#pragma unroll 16
    for (int d = 0; d < DD; d++) {
        float w1v = __ldg(&w1[(size_t)d * FF]);
        float wgv = __ldg(&wg[(size_t)d * FF]);
#pragma unroll
        for (int b = 0; b < BB; b++) {
            float hv = hs[b][d];
            au[b] += hv * w1v;
            ag[b] += hv * wgv;
        }
    }
    float bu = b1[(size_t)e * FF + f];
    float bv = bg[(size_t)e * FF + f];
#pragma unroll
    for (int b = 0; b < BB; b++)
        ug[((size_t)b * EE + e) * FF + f] = silu_f(au[b] + bu) * silu_f(ag[b] + bv);
}

// ---------------- expert down: split-F partials ----------------
__global__ void expert_w2p(const float* __restrict__ ug, const float* __restrict__ W2,
                           float* __restrict__ part)
{
    __shared__ float us[BB][512];
    const int e = blockIdx.y, fz = blockIdx.z;
    const int d = blockIdx.x * 128 + threadIdx.x;
    for (int i = threadIdx.x; i < BB * 512 / 4; i += 128) {
        int b = (i * 4) >> 9, f4 = (i * 4) & 511;
        *(float4*)&us[b][f4] = *(const float4*)&ug[((size_t)b * EE + e) * FF + fz * 512 + f4];
    }
    __syncthreads();
    const float* w = W2 + ((size_t)e * FF + fz * 512) * DD + d;
    float acc[BB] = {0.f, 0.f, 0.f, 0.f};
#pragma unroll 16
    for (int f = 0; f < 512; f++) {
        float wv = __ldg(&w[(size_t)f * DD]);
#pragma unroll
        for (int b = 0; b < BB; b++) acc[b] += us[b][f] * wv;
    }
#pragma unroll
    for (int b = 0; b < BB; b++)
        part[(size_t)fz * (BB * EE * DD) + ((size_t)b * EE + e) * DD + d] = acc[b];
}

// ---------------- combine attention (fp16 output, batch-chunked) ----------------
__global__ void combine_attn(const float* __restrict__ qh, const float* __restrict__ kh,
                             const float* __restrict__ vh, __half* __restrict__ out, int b0)
{
    extern __shared__ float sm[];
    const int PITCH = HH * 65;
    float* qsm = sm;
    float* ksm = sm + 16 * PITCH;
    float* vsm = sm + 32 * PITCH;
    const int b  = blockIdx.y + b0;
    const int t0 = blockIdx.x * 16;
    const int tid = threadIdx.x;

    for (int i = tid; i < NS * DD; i += 256) {
        int r = i >> 10, hd = i & 1023;
        int h = hd >> 6, d = hd & 63;
        int sw = r * PITCH + h * 65 + d;
        ksm[sw] = kh[(size_t)b * NS * DD + i];
        vsm[sw] = vh[(size_t)b * NS * DD + i];
        qsm[sw] = qh[((size_t)b * LL + t0) * DD + i];
    }
    __syncthreads();

    const int tt = tid >> 4;
    const int h  = tid & 15;

    float qreg[DH];
#pragma unroll
    for (int d = 0; d < DH; d++) qreg[d] = qsm[tt * PITCH + h * 65 + d];

    float sco[NS];
    float mx = -1e30f;
#pragma unroll
    for (int s = 0; s < NS; s++) {
        const float* kp = &ksm[s * PITCH + h * 65];
        float dot = 0.f;
#pragma unroll
        for (int d = 0; d < DH; d++) dot += qreg[d] * kp[d];
        dot *= 0.125f;
        sco[s] = dot;
        mx = fmaxf(mx, dot);
    }
    float sum = 0.f;
#pragma unroll
    for (int s = 0; s < NS; s++) { sco[s] = __expf(sco[s] - mx); sum += sco[s]; }
    float inv = 1.f / sum;

    float ov[DH];
#pragma unroll
    for (int d = 0; d < DH; d++) ov[d] = 0.f;
#pragma unroll
    for (int s = 0; s < NS; s++) {
        float pr = sco[s] * inv;
        const float* vp = &vsm[s * PITCH + h * 65];
#pragma unroll
        for (int d = 0; d < DH; d++) ov[d] += pr * vp[d];
    }
    __syncthreads();
#pragma unroll
    for (int d = 0; d < DH; d++) qsm[tt * PITCH + h * 65 + d] = ov[d];
    __syncthreads();
    for (int i = tid; i < NS * DD; i += 256) {
        int r = i >> 10, hd = i & 1023;
        int hh = hd >> 6, d = hd & 63;
        out[((size_t)b * LL + t0) * DD + i] = __float2half(qsm[r * PITCH + hh * 65 + d]);
    }
}

// ---------------- host launch ----------------
extern "C" void kernel_launch(void* const* d_in, const int* in_sizes, int n_in,
                              void* d_out, int out_size)
{
    const float* x    = (const float*)d_in[0];
    const float* sq   = (const float*)d_in[1];
    const float* dWq  = (const float*)d_in[2];
    const float* dWk  = (const float*)d_in[3];
    const float* dWv  = (const float*)d_in[4];
    const float* dWo  = (const float*)d_in[5];
    const float* dbq  = (const float*)d_in[6];
    const float* dbk  = (const float*)d_in[7];
    const float* dbv  = (const float*)d_in[8];
    const float* dbo  = (const float*)d_in[9];
    const float* cWq  = (const float*)d_in[10];
    const float* cWk  = (const float*)d_in[11];
    const float* cWv  = (const float*)d_in[12];
    const float* cWo  = (const float*)d_in[13];
    const float* cbq  = (const float*)d_in[14];
    const float* cbk  = (const float*)d_in[15];
    const float* cbv  = (const float*)d_in[16];
    const float* cbo  = (const float*)d_in[17];
    const float* elng = (const float*)d_in[18];
    const float* elnb = (const float*)d_in[19];
    const float* eW1  = (const float*)d_in[20];
    const float* eb1  = (const float*)d_in[21];
    const float* eWg  = (const float*)d_in[22];
    const float* ebg  = (const float*)d_in[23];
    const float* eW2  = (const float*)d_in[24];
    const float* eb2  = (const float*)d_in[25];
    float* out = (float*)d_out;

    float *qh1, *o, *hn, *ug, *qh2, *kh2, *vh2, *sc, *avp, *skp, *w2p, *kvp;
    __half *khh, *vhh, *xh, *wh, *a2h;
    cudaGetSymbolAddress((void**)&khh,  g_khh);
    cudaGetSymbolAddress((void**)&vhh,  g_vhh);
    cudaGetSymbolAddress((void**)&qh1,  g_qh1);
    cudaGetSymbolAddress((void**)&o,    g_o);
    cudaGetSymbolAddress((void**)&hn,   g_hn);
    cudaGetSymbolAddress((void**)&ug,   g_ug);
    cudaGetSymbolAddress((void**)&qh2,  g_qh2);
    cudaGetSymbolAddress((void**)&kh2,  g_kh2);
    cudaGetSymbolAddress((void**)&vh2,  g_vh2);
    cudaGetSymbolAddress((void**)&sc,   g_sc);
    cudaGetSymbolAddress((void**)&avp,  g_part);
    cudaGetSymbolAddress((void**)&skp,  g_skp);
    cudaGetSymbolAddress((void**)&w2p,  g_w2p);
    cudaGetSymbolAddress((void**)&kvp,  g_kvp);
    cudaGetSymbolAddress((void**)&xh,   g_xh);
    cudaGetSymbolAddress((void**)&wh,   g_wh);
    cudaGetSymbolAddress((void**)&a2h,  g_a2h);

    static cudaStream_t s2 = nullptr;
    static cudaEvent_t ev0, evW, evKH, evVH, evQH2, evPipe, evTail;
    if (!s2) {
        cudaStreamCreateWithFlags(&s2, cudaStreamNonBlocking);
        cudaEventCreateWithFlags(&ev0,   cudaEventDisableTiming);
        cudaEventCreateWithFlags(&evW,   cudaEventDisableTiming);
        cudaEventCreateWithFlags(&evKH,  cudaEventDisableTiming);
        cudaEventCreateWithFlags(&evVH,  cudaEventDisableTiming);
        cudaEventCreateWithFlags(&evQH2, cudaEventDisableTiming);
        cudaEventCreateWithFlags(&evPipe,cudaEventDisableTiming);
        cudaEventCreateWithFlags(&evTail,cudaEventDisableTiming);
    }

    const int SMEM_COMB = 3 * 16 * (HH * 65) * 4;
    cudaFuncSetAttribute(combine_attn, cudaFuncAttributeMaxDynamicSharedMemorySize, SMEM_COMB);
    cudaFuncSetAttribute(gemm_f16<float>,  cudaFuncAttributeMaxDynamicSharedMemorySize, GEMM_SMEM_H);
    cudaFuncSetAttribute(gemm_f16<__half>, cudaFuncAttributeMaxDynamicSharedMemorySize, GEMM_SMEM_H);

    dim3 gBig(DD / 128, (BB * LL) / 128);
    dim3 gHalf(DD / 128, (2 * LL) / 128);
    dim3 gSk(DD / 64, 8);
    const int W4 = DD * DD / 4;
    const int X4 = BB * LL * DD / 4;

    cudaEventRecord(ev0, 0);

    // L: x conversion   |   s2: weight conversion + dispatch-Q projection (concurrent)
    cvt_f16<<<X4 / 256, 256>>>(x, xh, X4);
    cudaStreamWaitEvent(s2, ev0, 0);
    cvt_w4_f16<<<dim3(W4 / 256, 4), 256, 0, s2>>>(dWk, dWv, cWq, cWo, wh);
    cudaEventRecord(evW, s2);
    gemm_q1<<<DD / 64, 256, 0, s2>>>(sq, dWq, dbq, qh1);

    // L: serial fp16 GEMM chain (kh, vh -> fp16 outputs; qh2 -> fp32)
    cudaStreamWaitEvent(0, evW, 0);
    gemm_f16<__half><<<gBig, 256, GEMM_SMEM_H>>>(xh, wh + 0 * DD * DD, dbk, khh, BB * LL, DD, DD);
    cudaEventRecord(evKH, 0);
    gemm_f16<__half><<<gBig, 256, GEMM_SMEM_H>>>(xh, wh + 1 * DD * DD, dbv, vhh, BB * LL, DD, DD);
    cudaEventRecord(evVH, 0);
    gemm_f16<float><<<gBig, 256, GEMM_SMEM_H>>>(xh, wh + 2 * DD * DD, cbq, qh2, BB * LL, DD, DD);
    cudaEventRecord(evQH2, 0);

    // s2: dispatch attention -> experts -> combine projections
    cudaStreamWaitEvent(s2, evKH, 0);
    disp_scores<<<dim3(LL / 128, HH, BB), 256, 0, s2>>>(qh1, khh, sc);
    disp_softmax<<<BB * HH * NS, 256, 0, s2>>>(sc);
    cudaStreamWaitEvent(s2, evVH, 0);
    disp_av<<<dim3(HH, BB, 16), 256, 0, s2>>>(sc, vhh, avp);

    gemm_skinny_red<<<gSk, 256, 0, s2>>>(avp, dWo, skp);
    skred_addsq_ln<<<BB * NS, 256, 0, s2>>>(skp, dbo, sq, o, elng, elnb, hn);

    expert_ug<<<dim3(FF / 128, EE), 128, 0, s2>>>(hn, eW1, eb1, eWg, ebg, ug);
    expert_w2p<<<dim3(DD / 128, EE, 8), 128, 0, s2>>>(ug, eW2, w2p);

    // combine K/V projections with w2-reduce fused into A-load
    gemm_skinny_dual_red<<<dim3(DD / 64, 8, 2), 256, 0, s2>>>(o, w2p, eb2, cWk, cWv,
                                                              kvp, kvp + 8 * 64 * DD);
    skinny_reduce_dual<<<dim3((64 * DD) / 256, 2), 256, 0, s2>>>(kvp, kvp + 8 * 64 * DD,
                                                                 cbk, cbv, kh2, vh2);
    cudaEventRecord(evPipe, s2);

    // tail: two 2-batch chunks on 2 streams
    cudaStreamWaitEvent(s2, evQH2, 0);
    combine_attn<<<dim3(LL / 16, 2), 256, SMEM_COMB, s2>>>(qh2, kh2, vh2, a2h, 2);
    gemm_f16<float><<<gHalf, 256, GEMM_SMEM_H, s2>>>(a2h + (size_t)2 * LL * DD, wh + 3 * DD * DD,
                                                     cbo, out + (size_t)2 * LL * DD, 2 * LL, DD, DD);
    cudaEventRecord(evTail, s2);

    cudaStreamWaitEvent(0, evPipe, 0);
    combine_attn<<<dim3(LL / 16, 2), 256, SMEM_COMB>>>(qh2, kh2, vh2, a2h, 0);
    gemm_f16<float><<<gHalf, 256, GEMM_SMEM_H>>>(a2h, wh + 3 * DD * DD, cbo, out, 2 * LL, DD, DD);

    cudaStreamWaitEvent(0, evTail, 0);
}

// round 14
// speedup vs baseline: 1.0475x; 1.0475x over previous
#include <cuda_runtime.h>
#include <cuda_fp16.h>
#include <math.h>

#define BB 4
#define LL 2048
#define DD 1024
#define HH 16
#define DH 64
#define NS 16
#define EE 16
#define FF 4096

// ---------------- scratch ----------------
__device__ __half g_khh [BB*LL*DD];
__device__ __half g_vhh [BB*LL*DD];
__device__ float  g_qh1 [NS*DD];
__device__ float  g_o   [BB*NS*DD];
__device__ float  g_hn  [BB*NS*DD];
__device__ float  g_ug  [BB*EE*FF];
__device__ float  g_qh2 [BB*LL*DD];
__device__ float  g_kh2 [BB*NS*DD];
__device__ float  g_vh2 [BB*NS*DD];
__device__ float  g_sc  [BB*HH*NS*LL];
__device__ float  g_part[16*BB*NS*DD];
__device__ float  g_skp [8*64*DD];
__device__ float  g_w2p [8*BB*EE*DD];
__device__ float  g_kvp [2*8*64*DD];
__device__ __half g_xh  [BB*LL*DD];
__device__ __half g_wh  [4*DD*DD];
__device__ __half g_a2h [BB*LL*DD];

__device__ __forceinline__ void cpa16(void* dst, const void* src) {
    unsigned d = (unsigned)__cvta_generic_to_shared(dst);
    asm volatile("cp.async.cg.shared.global [%0], [%1], 16;\n" :: "r"(d), "l"(src));
}
__device__ __forceinline__ void cpa_commit() {
    asm volatile("cp.async.commit_group;\n" ::: "memory");
}
__device__ __forceinline__ void cpa_wait2() {
    asm volatile("cp.async.wait_group 2;\n" ::: "memory");
}
__device__ __forceinline__ float ldcs(const float* p) {
    float v;
    asm volatile("ld.global.cs.f32 %0, [%1];" : "=f"(v) : "l"(p));
    return v;
}
__device__ __forceinline__ float silu_f(float x) { return x / (1.f + __expf(-x)); }

// ---------------- fp16 conversion pre-passes ----------------
__global__ void cvt_f16(const float* __restrict__ src, __half* __restrict__ dst, int n4)
{
    int i = blockIdx.x * 256 + threadIdx.x;
    if (i < n4) {
        float4 v = *(const float4*)&src[(size_t)i * 4];
        __half2 h0 = __floats2half2_rn(v.x, v.y);
        __half2 h1 = __floats2half2_rn(v.z, v.w);
        __half2* d2 = (__half2*)(dst + (size_t)i * 4);
        d2[0] = h0; d2[1] = h1;
    }
}

__global__ void cvt_w4_f16(const float* __restrict__ s0, const float* __restrict__ s1,
                           const float* __restrict__ s2, const float* __restrict__ s3,
                           __half* __restrict__ dst)
{
    int i = blockIdx.x * 256 + threadIdx.x;
    int y = blockIdx.y;
    const float* s = (y == 0) ? s0 : (y == 1) ? s1 : (y == 2) ? s2 : s3;
    float4 v = *(const float4*)&s[(size_t)i * 4];
    __half2 h0 = __floats2half2_rn(v.x, v.y);
    __half2 h1 = __floats2half2_rn(v.z, v.w);
    __half2* d2 = (__half2*)(dst + (size_t)y * DD * DD + (size_t)i * 4);
    d2[0] = h0; d2[1] = h1;
}

// ======================= fp16 tensor-core GEMM (m16n8k16 + ldmatrix) =======================
#define APITCH_H 40
#define BPITCH_H 136
#define ASTG_H (128*APITCH_H)
#define BSTG_H (32*BPITCH_H)
#define GEMM_SMEM_H (4 * (ASTG_H + BSTG_H) * 2)

template<typename OutT>
__global__ __launch_bounds__(256)
void gemm_f16(const __half* __restrict__ A, const __half* __restrict__ W,
              const float* __restrict__ bias, OutT* __restrict__ C,
              int M, int N, int K)
{
    extern __shared__ __half smh[];
    __half* As = smh;
    __half* Bs = smh + 4 * ASTG_H;

    const int tid  = threadIdx.x;
    const int wid  = tid >> 5;
    const int lane = tid & 31;
    const int g    = lane >> 2;
    const int tig  = lane & 3;
    const int wm0  = (wid >> 2) * 64;
    const int wn0  = (wid & 3) * 32;
    const int row0 = blockIdx.y * 128;
    const int col0 = blockIdx.x * 128;

    const int la = lane & 15;
    const int lb = (lane >> 4) * 8;

    const unsigned smem_base = (unsigned)__cvta_generic_to_shared(smh);
    const unsigned bs_base   = smem_base + 4 * ASTG_H * 2;

    const int NT = K >> 5;

    auto load_stage = [&](int tile, int st) {
        const int k0 = tile * 32;
        __half* as = As + st * ASTG_H;
        __half* bs = Bs + st * BSTG_H;
#pragma unroll
        for (int p = 0; p < 2; p++) {
            int c = tid + p * 256;
            int ar = c >> 2, ac = (c & 3) * 8;
            cpa16(&as[ar * APITCH_H + ac], &A[(size_t)(row0 + ar) * K + k0 + ac]);
            int br = c >> 4, bc = (c & 15) * 8;
            cpa16(&bs[br * BPITCH_H + bc], &W[(size_t)(k0 + br) * N + col0 + bc]);
        }
    };

    float acc[4][4][4];
#pragma unroll
    for (int i = 0; i < 4; i++)
#pragma unroll
        for (int j = 0; j < 4; j++)
#pragma unroll
            for (int c = 0; c < 4; c++) acc[i][j][c] = 0.f;

    load_stage(0, 0); cpa_commit();
    load_stage(1, 1); cpa_commit();
    load_stage(2, 2); cpa_commit();

    for (int i = 0; i < NT; i++) {
        cpa_wait2();
        __syncthreads();

        const int st = i & 3;
        const unsigned aBase = smem_base + (st * ASTG_H) * 2;
        const unsigned bBase = bs_base   + (st * BSTG_H) * 2;

#pragma unroll
        for (int ks = 0; ks < 2; ks++) {
            unsigned af[4][4];
#pragma unroll
            for (int mt = 0; mt < 4; mt++) {
                unsigned addr = aBase + (((wm0 + mt * 16 + la) * APITCH_H) + ks * 16 + lb) * 2;
                asm volatile("ldmatrix.sync.aligned.m8n8.x4.shared.b16 {%0,%1,%2,%3}, [%4];"
                             : "=r"(af[mt][0]), "=r"(af[mt][1]), "=r"(af[mt][2]), "=r"(af[mt][3])
                             : "r"(addr));
            }
            unsigned bf[4][2];
#pragma unroll
            for (int np = 0; np < 2; np++) {
                unsigned addr = bBase + (((ks * 16 + la) * BPITCH_H) + wn0 + np * 16 + lb) * 2;
                asm volatile("ldmatrix.sync.aligned.m8n8.x4.trans.shared.b16 {%0,%1,%2,%3}, [%4];"
                             : "=r"(bf[np * 2][0]), "=r"(bf[np * 2][1]),
                               "=r"(bf[np * 2 + 1][0]), "=r"(bf[np * 2 + 1][1])
                             : "r"(addr));
            }
#pragma unroll
            for (int mt = 0; mt < 4; mt++)
#pragma unroll
                for (int nt = 0; nt < 4; nt++) {
                    asm volatile(
                        "mma.sync.aligned.m16n8k16.row.col.f32.f16.f16.f32 "
                        "{%0,%1,%2,%3}, {%4,%5,%6,%7}, {%8,%9}, {%0,%1,%2,%3};\n"
                        : "+f"(acc[mt][nt][0]), "+f"(acc[mt][nt][1]),
                          "+f"(acc[mt][nt][2]), "+f"(acc[mt][nt][3])
                        : "r"(af[mt][0]), "r"(af[mt][1]), "r"(af[mt][2]), "r"(af[mt][3]),
                          "r"(bf[nt][0]), "r"(bf[nt][1]));
                }
        }

        if (i + 3 < NT) load_stage(i + 3, (i + 3) & 3);
        cpa_commit();
    }

#pragma unroll
    for (int mt = 0; mt < 4; mt++) {
#pragma unroll
        for (int nt = 0; nt < 4; nt++) {
            int r = row0 + wm0 + mt * 16 + g;
            int c = col0 + wn0 + nt * 8 + tig * 2;
            float b0v = bias[c], b1v = bias[c + 1];
            float o00 = acc[mt][nt][0] + b0v, o01 = acc[mt][nt][1] + b1v;
            float o10 = acc[mt][nt][2] + b0v, o11 = acc[mt][nt][3] + b1v;
            if constexpr (sizeof(OutT) == 4) {
                *(float2*)&C[(size_t)r * N + c] = make_float2(o00, o01);
                *(float2*)&C[(size_t)(r + 8) * N + c] = make_float2(o10, o11);
            } else {
                *(__half2*)&C[(size_t)r * N + c] = __floats2half2_rn(o00, o01);
                *(__half2*)&C[(size_t)(r + 8) * N + c] = __floats2half2_rn(o10, o11);
            }
        }
    }
}

// ======================= skinny split-K GEMM (M<=64, f32) =======================
template<int M>
__global__ void gemm_skinny(const float* __restrict__ A, const float* __restrict__ W,
                            float* __restrict__ part, int N, int K)
{
    __shared__ float As[64][132];
    const int tid = threadIdx.x;
    const int ks = blockIdx.y;
    const int n  = blockIdx.x * 64 + (tid & 63);
    const int mg = tid >> 6;
    const int k0 = ks * 128;

    for (int idx = tid; idx < M * 32; idx += 256) {
        int m = idx >> 5, c4 = (idx & 31) * 4;
        *(float4*)&As[m][c4] = *(const float4*)&A[(size_t)m * K + k0 + c4];
    }
    __syncthreads();

    const int MR = M / 4;
    float acc[MR];
#pragma unroll
    for (int r = 0; r < MR; r++) acc[r] = 0.f;

#pragma unroll 4
    for (int k = 0; k < 128; k++) {
        float wv = __ldg(&W[(size_t)(k0 + k) * N + n]);
#pragma unroll
        for (int r = 0; r < MR; r++) acc[r] += As[mg + 4 * r][k] * wv;
    }
#pragma unroll
    for (int r = 0; r < MR; r++)
        part[((size_t)ks * 64 + mg + 4 * r) * N + n] = acc[r];
}

// skinny GEMM with A = sum of 16 AV partials (fuses disp_reduce)
__global__ void gemm_skinny_red(const float* __restrict__ avp, const float* __restrict__ W,
                                float* __restrict__ part)
{
    __shared__ float As[64][132];
    const int tid = threadIdx.x;
    const int ks = blockIdx.y;
    const int n  = blockIdx.x * 64 + (tid & 63);
    const int mg = tid >> 6;
    const int k0 = ks * 128;

    for (int idx = tid; idx < 64 * 32; idx += 256) {
        int m = idx >> 5, c4 = (idx & 31) * 4;
        float4 s = make_float4(0.f, 0.f, 0.f, 0.f);
#pragma unroll
        for (int z = 0; z < 16; z++) {
            float4 p = *(const float4*)&avp[(size_t)z * (BB * NS * DD) + (size_t)m * DD + k0 + c4];
            s.x += p.x; s.y += p.y; s.z += p.z; s.w += p.w;
        }
        *(float4*)&As[m][c4] = s;
    }
    __syncthreads();

    float acc[16];
#pragma unroll
    for (int r = 0; r < 16; r++) acc[r] = 0.f;
#pragma unroll 4
    for (int k = 0; k < 128; k++) {
        float wv = __ldg(&W[(size_t)(k0 + k) * DD + n]);
#pragma unroll
        for (int r = 0; r < 16; r++) acc[r] += As[mg + 4 * r][k] * wv;
    }
#pragma unroll
    for (int r = 0; r < 16; r++)
        part[((size_t)ks * 64 + mg + 4 * r) * DD + n] = acc[r];
}

// dual skinny GEMM with A = o + b2 + sum8(w2 partials), fused in A-load (fuses w2_reduce)
__global__ void gemm_skinny_dual_red(const float* __restrict__ o, const float* __restrict__ w2p,
                                     const float* __restrict__ b2,
                                     const float* __restrict__ W0, const float* __restrict__ W1,
                                     float* __restrict__ p0, float* __restrict__ p1)
{
    __shared__ float As[64][132];
    const float* W = blockIdx.z ? W1 : W0;
    float* part    = blockIdx.z ? p1 : p0;
    const int tid = threadIdx.x;
    const int ks = blockIdx.y;
    const int n  = blockIdx.x * 64 + (tid & 63);
    const int mg = tid >> 6;
    const int k0 = ks * 128;

    for (int idx = tid; idx < 64 * 32; idx += 256) {
        int m = idx >> 5, c4 = (idx & 31) * 4;
        int e = m & (NS - 1);
        float4 s = *(const float4*)&o[(size_t)m * DD + k0 + c4];
        float4 bb = *(const float4*)&b2[(size_t)e * DD + k0 + c4];
        s.x += bb.x; s.y += bb.y; s.z += bb.z; s.w += bb.w;
#pragma unroll
        for (int z = 0; z < 8; z++) {
            float4 p = *(const float4*)&w2p[(size_t)z * (BB * EE * DD) + (size_t)m * DD + k0 + c4];
            s.x += p.x; s.y += p.y; s.z += p.z; s.w += p.w;
        }
        *(float4*)&As[m][c4] = s;
    }
    __syncthreads();

    float acc[16];
#pragma unroll
    for (int r = 0; r < 16; r++) acc[r] = 0.f;
#pragma unroll 4
    for (int k = 0; k < 128; k++) {
        float wv = __ldg(&W[(size_t)(k0 + k) * DD + n]);
#pragma unroll
        for (int r = 0; r < 16; r++) acc[r] += As[mg + 4 * r][k] * wv;
    }
#pragma unroll
    for (int r = 0; r < 16; r++)
        part[((size_t)ks * 64 + mg + 4 * r) * DD + n] = acc[r];
}

__global__ void skinny_reduce(const float* __restrict__ part, const float* __restrict__ bias,
                              float* __restrict__ C, int M, int N)
{
    int i = blockIdx.x * 256 + threadIdx.x;
    if (i < M * N) {
        int n = i & (N - 1);
        int m = i / N;
        float s = bias[n];
#pragma unroll
        for (int z = 0; z < 8; z++) s += part[((size_t)z * 64 + m) * N + n];
        C[i] = s;
    }
}

__global__ void skinny_reduce_dual(const float* __restrict__ p0, const float* __restrict__ p1,
                                   const float* __restrict__ bias0, const float* __restrict__ bias1,
                                   float* __restrict__ C0, float* __restrict__ C1)
{
    int i = blockIdx.x * 256 + threadIdx.x;
    const float* part = blockIdx.y ? p1 : p0;
    const float* bias = blockIdx.y ? bias1 : bias0;
    float* C          = blockIdx.y ? C1 : C0;
    int n = i & (DD - 1);
    int m = i / DD;
    float s = bias[n];
#pragma unroll
    for (int z = 0; z < 8; z++) s += part[((size_t)z * 64 + m) * DD + n];
    C[i] = s;
}

// fused: o = bias + slot_query + sum(skinny partials); hn = LayerNorm(o)
__global__ void skred_addsq_ln(const float* __restrict__ part, const float* __restrict__ bias,
                               const float* __restrict__ sq, float* __restrict__ o,
                               const float* __restrict__ gam, const float* __restrict__ bet,
                               float* __restrict__ hn)
{
    const int row = blockIdx.x;            // b*NS + s  (expert e == s)
    const int e = row & (NS - 1);
    const int tid = threadIdx.x;
    const int d4 = tid * 4;

    float4 v = *(const float4*)&bias[d4];
    float4 sv = *(const float4*)&sq[(size_t)e * DD + d4];
    v.x += sv.x; v.y += sv.y; v.z += sv.z; v.w += sv.w;
#pragma unroll
    for (int z = 0; z < 8; z++) {
        float4 p = *(const float4*)&part[((size_t)z * 64 + row) * DD + d4];
        v.x += p.x; v.y += p.y; v.z += p.z; v.w += p.w;
    }
    *(float4*)&o[(size_t)row * DD + d4] = v;

    float s1 = v.x + v.y + v.z + v.w;
    float s2 = v.x * v.x + v.y * v.y + v.z * v.z + v.w * v.w;
    __shared__ float r1[8], r2[8];
#pragma unroll
    for (int off = 16; off; off >>= 1) {
        s1 += __shfl_xor_sync(0xffffffffu, s1, off);
        s2 += __shfl_xor_sync(0xffffffffu, s2, off);
    }
    int wd = tid >> 5, ln = tid & 31;
    if (!ln) { r1[wd] = s1; r2[wd] = s2; }
    __syncthreads();
    if (tid < 32) {
        s1 = (ln < 8) ? r1[ln] : 0.f;
        s2 = (ln < 8) ? r2[ln] : 0.f;
#pragma unroll
        for (int off = 4; off; off >>= 1) {
            s1 += __shfl_xor_sync(0xffffffffu, s1, off);
            s2 += __shfl_xor_sync(0xffffffffu, s2, off);
        }
        if (!ln) { r1[0] = s1; r2[0] = s2; }
    }
    __syncthreads();
    float mu  = r1[0] * (1.f / DD);
    float var = r2[0] * (1.f / DD) - mu * mu;
    float inv = rsqrtf(var + 1e-5f);
    float4 gm = *(const float4*)&gam[(size_t)e * DD + d4];
    float4 bt = *(const float4*)&bet[(size_t)e * DD + d4];
    float4 hh;
    hh.x = (v.x - mu) * inv * gm.x + bt.x;
    hh.y = (v.y - mu) * inv * gm.y + bt.y;
    hh.z = (v.z - mu) * inv * gm.z + bt.z;
    hh.w = (v.w - mu) * inv * gm.w + bt.w;
    *(float4*)&hn[(size_t)row * DD + d4] = hh;
}

// ======================= dispatch attention (fp16 K/V) =======================
__global__ void disp_scores(const float* __restrict__ qh, const __half* __restrict__ khh,
                            float* __restrict__ sc)
{
    __shared__ float q[16][64];
    __shared__ float kt[128][65];
    const int j0 = blockIdx.x * 128;
    const int h  = blockIdx.y;
    const int b  = blockIdx.z;
    const int tid = threadIdx.x;

    for (int i = tid; i < NS * DH; i += 256) {
        int s = i >> 6, d = i & 63;
        q[s][d] = qh[(size_t)s * DD + h * DH + d];
    }
#pragma unroll
    for (int p = 0; p < 8; p++) {
        int idx = tid + p * 256;
        int jj = idx >> 4, d4 = (idx & 15) * 4;
        const __half2* src = (const __half2*)&khh[((size_t)b * LL + j0 + jj) * DD + h * DH + d4];
        float2 f0 = __half22float2(src[0]);
        float2 f1 = __half22float2(src[1]);
        kt[jj][d4 + 0] = f0.x; kt[jj][d4 + 1] = f0.y;
        kt[jj][d4 + 2] = f1.x; kt[jj][d4 + 3] = f1.y;
    }
    __syncthreads();

#pragma unroll
    for (int p = 0; p < 8; p++) {
        int idx = tid + p * 256;
        int s = idx >> 7, jj = idx & 127;
        float dot = 0.f;
#pragma unroll
        for (int d = 0; d < DH; d++) dot += q[s][d] * kt[jj][d];
        sc[(((size_t)b * HH + h) * NS + s) * LL + j0 + jj] = dot * 0.125f;
    }
}

__global__ void disp_softmax(float* __restrict__ sc)
{
    __shared__ float red[9];
    const int tid = threadIdx.x;
    float* r = sc + (size_t)blockIdx.x * LL;
    float v[8];
    float mx = -1e30f;
#pragma unroll
    for (int i = 0; i < 8; i++) { v[i] = r[tid + i * 256]; mx = fmaxf(mx, v[i]); }
#pragma unroll
    for (int o = 16; o; o >>= 1) mx = fmaxf(mx, __shfl_xor_sync(0xffffffffu, mx, o));
    int wd = tid >> 5, ln = tid & 31;
    if (!ln) red[wd] = mx;
    __syncthreads();
    if (tid < 32) {
        mx = (ln < 8) ? red[ln] : -1e30f;
#pragma unroll
        for (int o = 4; o; o >>= 1) mx = fmaxf(mx, __shfl_xor_sync(0xffffffffu, mx, o));
        if (!ln) red[8] = mx;
    }
    __syncthreads();
    mx = red[8];
    float sum = 0.f;
#pragma unroll
    for (int i = 0; i < 8; i++) { v[i] = __expf(v[i] - mx); sum += v[i]; }
#pragma unroll
    for (int o = 16; o; o >>= 1) sum += __shfl_xor_sync(0xffffffffu, sum, o);
    __syncthreads();
    if (!ln) red[wd] = sum;
    __syncthreads();
    if (tid < 32) {
        sum = (ln < 8) ? red[ln] : 0.f;
#pragma unroll
        for (int o = 4; o; o >>= 1) sum += __shfl_xor_sync(0xffffffffu, sum, o);
        if (!ln) red[8] = sum;
    }
    __syncthreads();
    float inv = 1.f / red[8];
#pragma unroll
    for (int i = 0; i < 8; i++) r[tid + i * 256] = v[i] * inv;
}

__global__ void disp_av(const float* __restrict__ sc, const __half* __restrict__ vhh,
                        float* __restrict__ part)
{
    __shared__ float p[16][132];
    __shared__ float vt[128][65];
    const int h = blockIdx.x, b = blockIdx.y, jz = blockIdx.z;
    const int j0 = jz * 128;
    const int tid = threadIdx.x;

#pragma unroll
    for (int q = 0; q < 2; q++) {
        int idx = tid + q * 256;
        int s = idx >> 5, j4 = (idx & 31) * 4;
        float4 v = *(const float4*)&sc[(((size_t)b * HH + h) * NS + s) * LL + j0 + j4];
        *(float4*)&p[s][j4] = v;
    }
#pragma unroll
    for (int q = 0; q < 8; q++) {
        int idx = tid + q * 256;
        int jj = idx >> 4, d4 = (idx & 15) * 4;
        const __half2* src = (const __half2*)&vhh[((size_t)b * LL + j0 + jj) * DD + h * DH + d4];
        float2 f0 = __half22float2(src[0]);
        float2 f1 = __half22float2(src[1]);
        vt[jj][d4 + 0] = f0.x; vt[jj][d4 + 1] = f0.y;
        vt[jj][d4 + 2] = f1.x; vt[jj][d4 + 3] = f1.y;
    }
    __syncthreads();

    float acc[4] = {0.f, 0.f, 0.f, 0.f};
#pragma unroll 4
    for (int jj = 0; jj < 128; jj++) {
#pragma unroll
        for (int k = 0; k < 4; k++) {
            int idx = tid + k * 256;
            int s = idx >> 6, d = idx & 63;
            acc[k] += p[s][jj] * vt[jj][d];
        }
    }
#pragma unroll
    for (int k = 0; k < 4; k++) {
        int idx = tid + k * 256;
        int s = idx >> 6, d = idx & 63;
        part[(size_t)jz * (BB * NS * DD) + ((size_t)b * NS + s) * DD + h * DH + d] = acc[k];
    }
}

// ---------------- expert up/gate (ld.cs streaming) ----------------
__global__ void expert_ug(const float* __restrict__ hn,
                          const float* __restrict__ W1, const float* __restrict__ b1,
                          const float* __restrict__ Wg, const float* __restrict__ bg,
                          float* __restrict__ ug)
{
    const int e = blockIdx.y;
    const int f = blockIdx.x * 128 + threadIdx.x;
    __shared__ float hs[BB][DD];
    for (int i = threadIdx.x; i < BB * DD / 4; i += 128) {
        int b = (i * 4) >> 10, d4 = (i * 4) & 1023;
        *(float4*)&hs[b][d4] = *(const float4*)&hn[((size_t)b * NS + e) * DD + d4];
    }
    __syncthreads();

    const float* w1 = W1 + (size_t)e * DD * FF + f;
    const float* wg = Wg + (size_t)e * DD * FF + f;
    float au[BB] = {0.f, 0.f, 0.f, 0.f};
    float ag[BB] = {0.f, 0.f, 0.f, 0.f};
#pragma unroll 16
    for (int d = 0; d < DD; d++) {
        float w1v = ldcs(&w1[(size_t)d * FF]);
        float wgv = ldcs(&wg[(size_t)d * FF]);
#pragma unroll
        for (int b = 0; b < BB; b++) {
            float hv = hs[b][d];
            au[b] += hv * w1v;
            ag[b] += hv * wgv;
        }
    }
    float bu = b1[(size_t)e * FF + f];
    float bv = bg[(size_t)e * FF + f];
#pragma unroll
    for (int b = 0; b < BB; b++)
        ug[((size_t)b * EE + e) * FF + f] = silu_f(au[b] + bu) * silu_f(ag[b] + bv);
}

// ---------------- expert down: split-F partials (ld.cs streaming) ----------------
__global__ void expert_w2p(const float* __restrict__ ug, const float* __restrict__ W2,
                           float* __restrict__ part)
{
    __shared__ float us[BB][512];
    const int e = blockIdx.y, fz = blockIdx.z;
    const int d = blockIdx.x * 128 + threadIdx.x;
    for (int i = threadIdx.x; i < BB * 512 / 4; i += 128) {
        int b = (i * 4) >> 9, f4 = (i * 4) & 511;
        *(float4*)&us[b][f4] = *(const float4*)&ug[((size_t)b * EE + e) * FF + fz * 512 + f4];
    }
    __syncthreads();
    const float* w = W2 + ((size_t)e * FF + fz * 512) * DD + d;
    float acc[BB] = {0.f, 0.f, 0.f, 0.f};
#pragma unroll 16
    for (int f = 0; f < 512; f++) {
        float wv = ldcs(&w[(size_t)f * DD]);
#pragma unroll
        for (int b = 0; b < BB; b++) acc[b] += us[b][f] * wv;
    }
#pragma unroll
    for (int b = 0; b < BB; b++)
        part[(size_t)fz * (BB * EE * DD) + ((size_t)b * EE + e) * DD + d] = acc[b];
}

// ---------------- combine attention (fp16 output, batch-chunked) ----------------
__global__ void combine_attn(const float* __restrict__ qh, const float* __restrict__ kh,
                             const float* __restrict__ vh, __half* __restrict__ out, int b0)
{
    extern __shared__ float sm[];
    const int PITCH = HH * 65;
    float* qsm = sm;
    float* ksm = sm + 16 * PITCH;
    float* vsm = sm + 32 * PITCH;
    const int b  = blockIdx.y + b0;
    const int t0 = blockIdx.x * 16;
    const int tid = threadIdx.x;

    for (int i = tid; i < NS * DD; i += 256) {
        int r = i >> 10, hd = i & 1023;
        int h = hd >> 6, d = hd & 63;
        int sw = r * PITCH + h * 65 + d;
        ksm[sw] = kh[(size_t)b * NS * DD + i];
        vsm[sw] = vh[(size_t)b * NS * DD + i];
        qsm[sw] = qh[((size_t)b * LL + t0) * DD + i];
    }
    __syncthreads();

    const int tt = tid >> 4;
    const int h  = tid & 15;

    float qreg[DH];
#pragma unroll
    for (int d = 0; d < DH; d++) qreg[d] = qsm[tt * PITCH + h * 65 + d];

    float sco[NS];
    float mx = -1e30f;
#pragma unroll
    for (int s = 0; s < NS; s++) {
        const float* kp = &ksm[s * PITCH + h * 65];
        float dot = 0.f;
#pragma unroll
        for (int d = 0; d < DH; d++) dot += qreg[d] * kp[d];
        dot *= 0.125f;
        sco[s] = dot;
        mx = fmaxf(mx, dot);
    }
    float sum = 0.f;
#pragma unroll
    for (int s = 0; s < NS; s++) { sco[s] = __expf(sco[s] - mx); sum += sco[s]; }
    float inv = 1.f / sum;

    float ov[DH];
#pragma unroll
    for (int d = 0; d < DH; d++) ov[d] = 0.f;
#pragma unroll
    for (int s = 0; s < NS; s++) {
        float pr = sco[s] * inv;
        const float* vp = &vsm[s * PITCH + h * 65];
#pragma unroll
        for (int d = 0; d < DH; d++) ov[d] += pr * vp[d];
    }
    __syncthreads();
#pragma unroll
    for (int d = 0; d < DH; d++) qsm[tt * PITCH + h * 65 + d] = ov[d];
    __syncthreads();
    for (int i = tid; i < NS * DD; i += 256) {
        int r = i >> 10, hd = i & 1023;
        int hh = hd >> 6, d = hd & 63;
        out[((size_t)b * LL + t0) * DD + i] = __float2half(qsm[r * PITCH + hh * 65 + d]);
    }
}

// ---------------- host launch ----------------
extern "C" void kernel_launch(void* const* d_in, const int* in_sizes, int n_in,
                              void* d_out, int out_size)
{
    const float* x    = (const float*)d_in[0];
    const float* sq   = (const float*)d_in[1];
    const float* dWq  = (const float*)d_in[2];
    const float* dWk  = (const float*)d_in[3];
    const float* dWv  = (const float*)d_in[4];
    const float* dWo  = (const float*)d_in[5];
    const float* dbq  = (const float*)d_in[6];
    const float* dbk  = (const float*)d_in[7];
    const float* dbv  = (const float*)d_in[8];
    const float* dbo  = (const float*)d_in[9];
    const float* cWq  = (const float*)d_in[10];
    const float* cWk  = (const float*)d_in[11];
    const float* cWv  = (const float*)d_in[12];
    const float* cWo  = (const float*)d_in[13];
    const float* cbq  = (const float*)d_in[14];
    const float* cbk  = (const float*)d_in[15];
    const float* cbv  = (const float*)d_in[16];
    const float* cbo  = (const float*)d_in[17];
    const float* elng = (const float*)d_in[18];
    const float* elnb = (const float*)d_in[19];
    const float* eW1  = (const float*)d_in[20];
    const float* eb1  = (const float*)d_in[21];
    const float* eWg  = (const float*)d_in[22];
    const float* ebg  = (const float*)d_in[23];
    const float* eW2  = (const float*)d_in[24];
    const float* eb2  = (const float*)d_in[25];
    float* out = (float*)d_out;

    float *qh1, *o, *hn, *ug, *qh2, *kh2, *vh2, *sc, *avp, *skp, *w2p, *kvp;
    __half *khh, *vhh, *xh, *wh, *a2h;
    cudaGetSymbolAddress((void**)&khh,  g_khh);
    cudaGetSymbolAddress((void**)&vhh,  g_vhh);
    cudaGetSymbolAddress((void**)&qh1,  g_qh1);
    cudaGetSymbolAddress((void**)&o,    g_o);
    cudaGetSymbolAddress((void**)&hn,   g_hn);
    cudaGetSymbolAddress((void**)&ug,   g_ug);
    cudaGetSymbolAddress((void**)&qh2,  g_qh2);
    cudaGetSymbolAddress((void**)&kh2,  g_kh2);
    cudaGetSymbolAddress((void**)&vh2,  g_vh2);
    cudaGetSymbolAddress((void**)&sc,   g_sc);
    cudaGetSymbolAddress((void**)&avp,  g_part);
    cudaGetSymbolAddress((void**)&skp,  g_skp);
    cudaGetSymbolAddress((void**)&w2p,  g_w2p);
    cudaGetSymbolAddress((void**)&kvp,  g_kvp);
    cudaGetSymbolAddress((void**)&xh,   g_xh);
    cudaGetSymbolAddress((void**)&wh,   g_wh);
    cudaGetSymbolAddress((void**)&a2h,  g_a2h);

    static cudaStream_t s2 = nullptr;
    static cudaEvent_t ev0, evW, evKH, evVH, evQH2, evPipe, evTail;
    if (!s2) {
        cudaStreamCreateWithFlags(&s2, cudaStreamNonBlocking);
        cudaEventCreateWithFlags(&ev0,   cudaEventDisableTiming);
        cudaEventCreateWithFlags(&evW,   cudaEventDisableTiming);
        cudaEventCreateWithFlags(&evKH,  cudaEventDisableTiming);
        cudaEventCreateWithFlags(&evVH,  cudaEventDisableTiming);
        cudaEventCreateWithFlags(&evQH2, cudaEventDisableTiming);
        cudaEventCreateWithFlags(&evPipe,cudaEventDisableTiming);
        cudaEventCreateWithFlags(&evTail,cudaEventDisableTiming);
    }

    const int SMEM_COMB = 3 * 16 * (HH * 65) * 4;
    cudaFuncSetAttribute(combine_attn, cudaFuncAttributeMaxDynamicSharedMemorySize, SMEM_COMB);
    cudaFuncSetAttribute(gemm_f16<float>,  cudaFuncAttributeMaxDynamicSharedMemorySize, GEMM_SMEM_H);
    cudaFuncSetAttribute(gemm_f16<__half>, cudaFuncAttributeMaxDynamicSharedMemorySize, GEMM_SMEM_H);

    dim3 gBig(DD / 128, (BB * LL) / 128);
    dim3 gHalf(DD / 128, (2 * LL) / 128);
    dim3 gSk(DD / 64, 8);
    const int W4 = DD * DD / 4;
    const int X4 = BB * LL * DD / 4;

    cudaEventRecord(ev0, 0);

    // L: x conversion   |   s2: weight conversion + dispatch-Q projection (concurrent)
    cvt_f16<<<X4 / 256, 256>>>(x, xh, X4);
    cudaStreamWaitEvent(s2, ev0, 0);
    cvt_w4_f16<<<dim3(W4 / 256, 4), 256, 0, s2>>>(dWk, dWv, cWq, cWo, wh);
    cudaEventRecord(evW, s2);
    gemm_skinny<16><<<gSk, 256, 0, s2>>>(sq, dWq, skp, DD, DD);
    skinny_reduce<<<(16 * DD) / 256, 256, 0, s2>>>(skp, dbq, qh1, 16, DD);

    // L: serial fp16 GEMM chain (kh, vh -> fp16 outputs; qh2 -> fp32)
    cudaStreamWaitEvent(0, evW, 0);
    gemm_f16<__half><<<gBig, 256, GEMM_SMEM_H>>>(xh, wh + 0 * DD * DD, dbk, khh, BB * LL, DD, DD);
    cudaEventRecord(evKH, 0);
    gemm_f16<__half><<<gBig, 256, GEMM_SMEM_H>>>(xh, wh + 1 * DD * DD, dbv, vhh, BB * LL, DD, DD);
    cudaEventRecord(evVH, 0);
    gemm_f16<float><<<gBig, 256, GEMM_SMEM_H>>>(xh, wh + 2 * DD * DD, cbq, qh2, BB * LL, DD, DD);
    cudaEventRecord(evQH2, 0);

    // s2: dispatch attention -> experts -> combine projections
    cudaStreamWaitEvent(s2, evKH, 0);
    disp_scores<<<dim3(LL / 128, HH, BB), 256, 0, s2>>>(qh1, khh, sc);
    disp_softmax<<<BB * HH * NS, 256, 0, s2>>>(sc);
    cudaStreamWaitEvent(s2, evVH, 0);
    disp_av<<<dim3(HH, BB, 16), 256, 0, s2>>>(sc, vhh, avp);

    gemm_skinny_red<<<gSk, 256, 0, s2>>>(avp, dWo, skp);
    skred_addsq_ln<<<BB * NS, 256, 0, s2>>>(skp, dbo, sq, o, elng, elnb, hn);

    expert_ug<<<dim3(FF / 128, EE), 128, 0, s2>>>(hn, eW1, eb1, eWg, ebg, ug);
    expert_w2p<<<dim3(DD / 128, EE, 8), 128, 0, s2>>>(ug, eW2, w2p);

    // combine K/V projections with w2-reduce fused into A-load
    gemm_skinny_dual_red<<<dim3(DD / 64, 8, 2), 256, 0, s2>>>(o, w2p, eb2, cWk, cWv,
                                                              kvp, kvp + 8 * 64 * DD);
    skinny_reduce_dual<<<dim3((64 * DD) / 256, 2), 256, 0, s2>>>(kvp, kvp + 8 * 64 * DD,
                                                                 cbk, cbv, kh2, vh2);
    cudaEventRecord(evPipe, s2);

    // tail: two 2-batch chunks on 2 streams
    cudaStreamWaitEvent(s2, evQH2, 0);
    combine_attn<<<dim3(LL / 16, 2), 256, SMEM_COMB, s2>>>(qh2, kh2, vh2, a2h, 2);
    gemm_f16<float><<<gHalf, 256, GEMM_SMEM_H, s2>>>(a2h + (size_t)2 * LL * DD, wh + 3 * DD * DD,
                                                     cbo, out + (size_t)2 * LL * DD, 2 * LL, DD, DD);
    cudaEventRecord(evTail, s2);

    cudaStreamWaitEvent(0, evPipe, 0);
    combine_attn<<<dim3(LL / 16, 2), 256, SMEM_COMB>>>(qh2, kh2, vh2, a2h, 0);
    gemm_f16<float><<<gHalf, 256, GEMM_SMEM_H>>>(a2h, wh + 3 * DD * DD, cbo, out, 2 * LL, DD, DD);

    cudaStreamWaitEvent(0, evTail, 0);
}